// round 4
// baseline (speedup 1.0000x reference)
#include <cuda_runtime.h>
#include <cuda_bf16.h>

// Controlled X_theta on a 16-amp state: ctrl bit CB=1 -> [[0,-ie],[-i conj(e),0]]
// on target bit TB, e = (er, ei) = e^{i theta/2}.
template <int CB, int TB>
__device__ __forceinline__ void cu_g(float (&sr)[16], float (&si)[16],
                                     float er, float ei) {
#pragma unroll
    for (int i = 0; i < 16; i++) {
        if (!(i & CB) || (i & TB)) continue;
        const int j = i | TB;
        float t0r = sr[i], t0i = si[i], t1r = sr[j], t1i = si[j];
        // t0' = (-i e) * t1 = (ei, -er) * t1
        sr[i] = fmaf(ei, t1r, er * t1i);
        si[i] = fmaf(ei, t1i, -er * t1r);
        // t1' = (-i conj(e)) * t0 = (-ei, -er) * t0
        sr[j] = fmaf(er, t0i, -ei * t0r);
        si[j] = -fmaf(ei, t0i, er * t0r);
    }
}

// RX(theta) on target bit TB: [[c, -is],[-is, c]].
template <int TB>
__device__ __forceinline__ void rx_g(float (&sr)[16], float (&si)[16],
                                     float c, float s) {
#pragma unroll
    for (int i = 0; i < 16; i++) {
        if (i & TB) continue;
        const int j = i | TB;
        float a0r = sr[i], a0i = si[i], a1r = sr[j], a1i = si[j];
        sr[i] = fmaf(c, a0r, s * a1i);
        si[i] = fmaf(c, a0i, -s * a1r);
        sr[j] = fmaf(c, a1r, s * a0i);
        si[j] = fmaf(c, a1i, -s * a0r);
    }
}

// Two threads per patch: even thread = wire0 |0> branch, odd = |1> branch.
// Wire0 is never a gate target, so both branches run the same instruction
// stream; only CPhase differs (per-thread constants). H gates + Z-measure
// fold into ev = sum_k Re(psi_lo[k] * conj(psi_hi[k])).
#define TPB 128

__global__ void __launch_bounds__(TPB, 7)
sim_k(const float* __restrict__ x, const float* __restrict__ thetas,
      const float* __restrict__ phis, float* __restrict__ out) {
    __shared__ float2 sh_e[12];  // e^{i theta/2}
    __shared__ float2 sh_p[3];   // e^{i phi}

    int tid = threadIdx.x;
    if (tid < 12) {
        float s, c;
        __sincosf(0.5f * thetas[tid], &s, &c);
        sh_e[tid] = make_float2(c, s);
    } else if (tid < 15) {
        float s, c;
        __sincosf(phis[tid - 12], &s, &c);
        sh_p[tid - 12] = make_float2(c, s);
    }
    __syncthreads();

    int gt = blockIdx.x * TPB + tid;
    int patch = gt >> 1;
    int br = gt & 1;  // 0 = wire0 |0> branch, 1 = |1> branch

    int b = patch >> 14;
    int rem = patch & 16383;
    int h2 = rem >> 7;
    int w2 = rem & 127;
    const float* xb = x + (size_t)b * 196608 + (size_t)h2 * 512 + (size_t)w2 * 2;

    // Layer L uses exactly channel L's 2x2 patch (pix idx = ch*4 + dy*2 + dx).
    // Reload + sincos per layer keeps only 8 trig regs live.
    float tc[4], ts[4];
    {
        float2 v0 = *reinterpret_cast<const float2*>(xb);
        float2 v1 = *reinterpret_cast<const float2*>(xb + 256);
        __sincosf(0.5f * v0.x, &ts[0], &tc[0]);
        __sincosf(0.5f * v0.y, &ts[1], &tc[1]);
        __sincosf(0.5f * v1.x, &ts[2], &tc[2]);
        __sincosf(0.5f * v1.y, &ts[3], &tc[3]);
    }

    // State over wires 1..4: index k = b<<3 | c<<2 | d<<1 | e.
    float sr[16], si[16];

    // Layer-0 RX block == product state: amp(k) = prod q * (-i)^popcount(k).
    {
        float ab[4], de[4];
        ab[0] = tc[0] * tc[1]; ab[1] = tc[0] * ts[1];
        ab[2] = ts[0] * tc[1]; ab[3] = ts[0] * ts[1];
        de[0] = tc[2] * tc[3]; de[1] = tc[2] * ts[3];
        de[2] = ts[2] * tc[3]; de[3] = ts[2] * ts[3];
#pragma unroll
        for (int k = 0; k < 16; k++) {
            float m = ab[k >> 2] * de[k & 3];
            int pc = __popc(k) & 3;  // compile-time folded
            sr[k] = (pc == 0) ? m : (pc == 2) ? -m : 0.0f;
            si[k] = (pc == 1) ? -m : (pc == 3) ? m : 0.0f;
        }
    }

#pragma unroll
    for (int L = 0; L < 3; L++) {
        if (L > 0) {
            float2 v0 = *reinterpret_cast<const float2*>(xb + L * 65536);
            float2 v1 = *reinterpret_cast<const float2*>(xb + L * 65536 + 256);
            __sincosf(0.5f * v0.x, &ts[0], &tc[0]);
            __sincosf(0.5f * v0.y, &ts[1], &tc[1]);
            __sincosf(0.5f * v1.x, &ts[2], &tc[2]);
            __sincosf(0.5f * v1.y, &ts[3], &tc[3]);
            rx_g<8>(sr, si, tc[0], ts[0]);
            rx_g<4>(sr, si, tc[1], ts[1]);
            rx_g<2>(sr, si, tc[2], ts[2]);
            rx_g<1>(sr, si, tc[3], ts[3]);
        }
        float2 e;
        e = sh_e[4 * L + 0]; cu_g<8, 4>(sr, si, e.x, e.y);
        e = sh_e[4 * L + 1]; cu_g<4, 2>(sr, si, e.x, e.y);
        e = sh_e[4 * L + 2]; cu_g<2, 1>(sr, si, e.x, e.y);
        e = sh_e[4 * L + 3]; cu_g<1, 8>(sr, si, e.x, e.y);
        // CPhase(phi_L) on wires (0,1): only the |1> branch (odd thread)
        // phases its b-bit=1 amplitudes. Uniform code via per-thread consts.
        float2 ph = sh_p[L];
        float phc = br ? ph.x : 1.0f;
        float phs = br ? ph.y : 0.0f;
#pragma unroll
        for (int j = 8; j < 16; j++) {
            float r = sr[j], m = si[j];
            sr[j] = fmaf(phc, r, -phs * m);
            si[j] = fmaf(phc, m, phs * r);
        }
    }

    // <Z_0> = sum_k Re(psi_lo[k] * conj(psi_hi[k])) — symmetric, both threads
    // compute the same value; even thread writes.
    float ev = 0.f;
#pragma unroll
    for (int k = 0; k < 16; k++) {
        float orr = __shfl_xor_sync(0xffffffffu, sr[k], 1);
        float oii = __shfl_xor_sync(0xffffffffu, si[k], 1);
        ev = fmaf(sr[k], orr, ev);
        ev = fmaf(si[k], oii, ev);
    }
    if (!br) out[patch] = ev;
}

extern "C" void kernel_launch(void* const* d_in, const int* in_sizes, int n_in,
                              void* d_out, int out_size) {
    const float* x = nullptr;
    const float* thetas = nullptr;
    const float* phis = nullptr;
    for (int i = 0; i < n_in; i++) {
        if (in_sizes[i] == 12) thetas = (const float*)d_in[i];
        else if (in_sizes[i] == 3) phis = (const float*)d_in[i];
        else x = (const float*)d_in[i];
    }
    float* out = (float*)d_out;

    int grid = (2 * out_size + TPB - 1) / TPB;  // 4096 for P = 262144
    sim_k<<<grid, TPB>>>(x, thetas, phis, out);
}

// round 5
// speedup vs baseline: 1.1412x; 1.1412x over previous
#include <cuda_runtime.h>
#include <cuda_bf16.h>

// RX(theta) on target bit TB over first N amplitudes: [[c, -is],[-is, c]].
template <int N, int TB>
__device__ __forceinline__ void rx_g(float (&sr)[32], float (&si)[32],
                                     float c, float s) {
#pragma unroll
    for (int i = 0; i < N; i++) {
        if (i & TB) continue;
        const int j = i | TB;
        float a0r = sr[i], a0i = si[i], a1r = sr[j], a1i = si[j];
        sr[i] = fmaf(c, a0r, s * a1i);
        si[i] = fmaf(c, a0i, -s * a1r);
        sr[j] = fmaf(c, a1r, s * a0i);
        si[j] = fmaf(c, a1i, -s * a0r);
    }
}

// Controlled X_theta: ctrl bit CB=1 -> [[0,-ie],[-i conj(e),0]] on TB,
// e = (er, ei) = e^{i theta/2}.
template <int N, int CB, int TB>
__device__ __forceinline__ void cu_g(float (&sr)[32], float (&si)[32],
                                     float er, float ei) {
#pragma unroll
    for (int i = 0; i < N; i++) {
        if (!(i & CB) || (i & TB)) continue;
        const int j = i | TB;
        float t0r = sr[i], t0i = si[i], t1r = sr[j], t1i = si[j];
        // t0' = (-i e) * t1 = (ei, -er) * t1
        sr[i] = fmaf(ei, t1r, er * t1i);
        si[i] = fmaf(ei, t1i, -er * t1r);
        // t1' = (-i conj(e)) * t0 = (-ei, -er) * t0
        sr[j] = fmaf(er, t0i, -ei * t0r);
        si[j] = -fmaf(ei, t0i, er * t0r);
    }
}

// One thread per patch, full 32-amp state in registers.
// launch_bounds(128,7): 72-reg cap -> 7 blocks/SM = 28 resident warps;
// grid 2048 over 1036 concurrent blocks = 1.977 waves -> 98.8% tail util.
#define TPB 128

__global__ void __launch_bounds__(TPB, 7)
sim_k(const float* __restrict__ x, const float* __restrict__ thetas,
      const float* __restrict__ phis, float* __restrict__ out) {
    __shared__ float2 sh_e[12];  // e^{i theta/2}
    __shared__ float2 sh_p[3];   // e^{i phi}

    int tid = threadIdx.x;
    if (tid < 12) {
        float s, c;
        __sincosf(0.5f * thetas[tid], &s, &c);
        sh_e[tid] = make_float2(c, s);
    } else if (tid < 15) {
        float s, c;
        __sincosf(phis[tid - 12], &s, &c);
        sh_p[tid - 12] = make_float2(c, s);
    }
    __syncthreads();

    int p = blockIdx.x * TPB + tid;
    int b = p >> 14;
    int rem = p & 16383;
    int h2 = rem >> 7;
    int w2 = rem & 127;
    const float* xb = x + (size_t)b * 196608 + (size_t)h2 * 512 + (size_t)w2 * 2;

    // Layer L consumes exactly channel L's 2x2 pixels; reload + sincos per
    // layer keeps only 8 trig registers live.
    float tc[4], ts[4];
    {
        float2 v0 = *reinterpret_cast<const float2*>(xb);
        float2 v1 = *reinterpret_cast<const float2*>(xb + 256);
        __sincosf(0.5f * v0.x, &ts[0], &tc[0]);
        __sincosf(0.5f * v0.y, &ts[1], &tc[1]);
        __sincosf(0.5f * v1.x, &ts[2], &tc[2]);
        __sincosf(0.5f * v1.y, &ts[3], &tc[3]);
    }

    // State index = a<<4 | b<<3 | c<<2 | d<<1 | e (wires 0..4).
    // Wire0 untouched until the first CPhase -> layer 0 on the 16-dim
    // subspace; the two H branches are identical until the fork. Both H's,
    // normalizations and Z-measure fold into ev = sum Re(psi_lo psi_hi^*).
    float sr[32], si[32];

    // Layer-0 RX block == product state: amp(k) = prod q * (-i)^popcount(k).
    {
        float ab[4], de[4];
        ab[0] = tc[0] * tc[1]; ab[1] = tc[0] * ts[1];
        ab[2] = ts[0] * tc[1]; ab[3] = ts[0] * ts[1];
        de[0] = tc[2] * tc[3]; de[1] = tc[2] * ts[3];
        de[2] = ts[2] * tc[3]; de[3] = ts[2] * ts[3];
#pragma unroll
        for (int k = 0; k < 16; k++) {
            float m = ab[k >> 2] * de[k & 3];
            int pc = __popc(k) & 3;  // compile-time folded
            sr[k] = (pc == 0) ? m : (pc == 2) ? -m : 0.0f;
            si[k] = (pc == 1) ? -m : (pc == 3) ? m : 0.0f;
        }
    }

    // Layer-0 CU gates on the 16-dim subspace.
    float2 e;
    e = sh_e[0]; cu_g<16, 8, 4>(sr, si, e.x, e.y);
    e = sh_e[1]; cu_g<16, 4, 2>(sr, si, e.x, e.y);
    e = sh_e[2]; cu_g<16, 2, 1>(sr, si, e.x, e.y);
    e = sh_e[3]; cu_g<16, 1, 8>(sr, si, e.x, e.y);

    // Fork: a=1 branch gets CPhase(phi_0) on its b=1 amplitudes.
    {
        float2 ph = sh_p[0];
#pragma unroll
        for (int j = 0; j < 16; j++) {
            if (j & 8) {
                sr[16 + j] = fmaf(ph.x, sr[j], -ph.y * si[j]);
                si[16 + j] = fmaf(ph.x, si[j], ph.y * sr[j]);
            } else {
                sr[16 + j] = sr[j];
                si[16 + j] = si[j];
            }
        }
    }

    // Layers 1, 2 on the full 32-dim state.
#pragma unroll
    for (int L = 1; L < 3; L++) {
        {
            float2 v0 = *reinterpret_cast<const float2*>(xb + L * 65536);
            float2 v1 = *reinterpret_cast<const float2*>(xb + L * 65536 + 256);
            __sincosf(0.5f * v0.x, &ts[0], &tc[0]);
            __sincosf(0.5f * v0.y, &ts[1], &tc[1]);
            __sincosf(0.5f * v1.x, &ts[2], &tc[2]);
            __sincosf(0.5f * v1.y, &ts[3], &tc[3]);
        }
        rx_g<32, 8>(sr, si, tc[0], ts[0]);
        rx_g<32, 4>(sr, si, tc[1], ts[1]);
        rx_g<32, 2>(sr, si, tc[2], ts[2]);
        rx_g<32, 1>(sr, si, tc[3], ts[3]);
        e = sh_e[4 * L + 0]; cu_g<32, 8, 4>(sr, si, e.x, e.y);
        e = sh_e[4 * L + 1]; cu_g<32, 4, 2>(sr, si, e.x, e.y);
        e = sh_e[4 * L + 2]; cu_g<32, 2, 1>(sr, si, e.x, e.y);
        e = sh_e[4 * L + 3]; cu_g<32, 1, 8>(sr, si, e.x, e.y);
        // CPhase(phi_L) on wires 0,1: bit4 & bit3 set -> indices 24..31.
        float2 ph = sh_p[L];
#pragma unroll
        for (int j = 24; j < 32; j++) {
            float r = sr[j], m = si[j];
            sr[j] = fmaf(ph.x, r, -ph.y * m);
            si[j] = fmaf(ph.x, m, ph.y * r);
        }
    }

    // <Z_0> = sum_k Re(psi_lo[k] * conj(psi_hi[k])).
    float ev = 0.f;
#pragma unroll
    for (int j = 0; j < 16; j++) {
        ev = fmaf(sr[j], sr[j + 16], ev);
        ev = fmaf(si[j], si[j + 16], ev);
    }
    out[p] = ev;
}

extern "C" void kernel_launch(void* const* d_in, const int* in_sizes, int n_in,
                              void* d_out, int out_size) {
    const float* x = nullptr;
    const float* thetas = nullptr;
    const float* phis = nullptr;
    for (int i = 0; i < n_in; i++) {
        if (in_sizes[i] == 12) thetas = (const float*)d_in[i];
        else if (in_sizes[i] == 3) phis = (const float*)d_in[i];
        else x = (const float*)d_in[i];
    }
    float* out = (float*)d_out;

    int grid = (out_size + TPB - 1) / TPB;  // 2048 for P = 262144
    sim_k<<<grid, TPB>>>(x, thetas, phis, out);
}